// round 12
// baseline (speedup 1.0000x reference)
#include <cuda_runtime.h>
#include <cstdint>
#include <math.h>

// Problem constants (fixed shapes)
#define T    2048
#define DM   1024
#define NE   8
#define FF   4096

#define KC   32            // K floats per chunk
#define PAD  36            // smem row stride in floats (32 + 4)

// ---------------- scratch (static device globals; no allocation) ----------------
__device__ int   g_count[NE];
__device__ int   g_cursor[NE];
__device__ int   g_offset[NE];
__device__ int   g_topk_idx[T * 2];
__device__ float g_topk_w[T * 2];
__device__ int   g_tok[2 * T];
__device__ float g_wgt[2 * T];
__device__ float g_inter[(size_t)(2 * T) * FF];   // 64 MB fp32 scratch

#define DEVINL __device__ __forceinline__

DEVINL uint32_t smem_u32(const void* p) {
    uint32_t a;
    asm("{ .reg .u64 t; cvta.to.shared.u64 t, %1; cvt.u32.u64 %0, t; }" : "=r"(a) : "l"(p));
    return a;
}

DEVINL uint32_t to_tf32(float f) {
    uint32_t r;
    asm("cvt.rna.tf32.f32 %0, %1;" : "=r"(r) : "f"(f));
    return r;
}
DEVINL uint4 to_tf32_v4(float4 v) {
    return make_uint4(to_tf32(v.x), to_tf32(v.y), to_tf32(v.z), to_tf32(v.w));
}

DEVINL void mma_tf32(float* d, const uint32_t* a, const uint32_t* b) {
    asm volatile(
        "mma.sync.aligned.m16n8k8.row.col.f32.tf32.tf32.f32 "
        "{%0,%1,%2,%3}, {%4,%5,%6,%7}, {%8,%9}, {%0,%1,%2,%3};"
        : "+f"(d[0]), "+f"(d[1]), "+f"(d[2]), "+f"(d[3])
        : "r"(a[0]), "r"(a[1]), "r"(a[2]), "r"(a[3]), "r"(b[0]), "r"(b[1]));
}

DEVINL void ldsm_x4(uint32_t addr, uint32_t* r) {
    asm volatile("ldmatrix.sync.aligned.m8n8.x4.shared.b16 {%0,%1,%2,%3}, [%4];"
        : "=r"(r[0]), "=r"(r[1]), "=r"(r[2]), "=r"(r[3]) : "r"(addr));
}

// ---------------- init ----------------
__global__ void init_kernel() {
    int i = threadIdx.x;
    if (i < NE) { g_count[i] = 0; g_cursor[i] = 0; }
}

// ---------------- router ----------------
__global__ void router_kernel(const float* __restrict__ x,
                              const float* __restrict__ gw,
                              float* __restrict__ logits_out) {
    int t = blockIdx.x;
    int warp = threadIdx.x >> 5;
    int lane = threadIdx.x & 31;
    const float* xr = x + (size_t)t * DM;
    const float* gr = gw + (size_t)warp * DM;
    float s = 0.f;
    for (int j = lane; j < DM; j += 32) s += xr[j] * gr[j];
    #pragma unroll
    for (int o = 16; o > 0; o >>= 1) s += __shfl_xor_sync(0xFFFFFFFFu, s, o);

    __shared__ float lg[NE];
    if (lane == 0) lg[warp] = s;
    __syncthreads();

    if (threadIdx.x == 0) {
        float mx = lg[0];
        #pragma unroll
        for (int e = 1; e < NE; e++) mx = fmaxf(mx, lg[e]);
        float p[NE];
        #pragma unroll
        for (int e = 0; e < NE; e++) p[e] = expf(lg[e] - mx);
        int i0 = 0;
        #pragma unroll
        for (int e = 1; e < NE; e++) if (p[e] > p[i0]) i0 = e;
        int i1 = -1;
        #pragma unroll
        for (int e = 0; e < NE; e++) {
            if (e == i0) continue;
            if (i1 < 0 || p[e] > p[i1]) i1 = e;
        }
        float inv = 1.f / (p[i0] + p[i1]);
        g_topk_idx[t * 2 + 0] = i0;
        g_topk_idx[t * 2 + 1] = i1;
        g_topk_w[t * 2 + 0] = p[i0] * inv;
        g_topk_w[t * 2 + 1] = p[i1] * inv;
        atomicAdd(&g_count[i0], 1);
        atomicAdd(&g_count[i1], 1);
        #pragma unroll
        for (int e = 0; e < NE; e++) logits_out[(size_t)t * NE + e] = lg[e];
    }
}

// ---------------- offsets + assignment (single block) ----------------
__global__ void assign_kernel() {
    if (threadIdx.x == 0) {
        int o = 0;
        #pragma unroll
        for (int e = 0; e < NE; e++) { g_offset[e] = o; o += g_count[e]; }
    }
    __syncthreads();
    for (int t = threadIdx.x; t < T; t += blockDim.x) {
        #pragma unroll
        for (int k = 0; k < 2; k++) {
            int e = g_topk_idx[t * 2 + k];
            int pos = atomicAdd(&g_cursor[e], 1);
            int g = g_offset[e] + pos;
            g_tok[g] = t;
            g_wgt[g] = g_topk_w[t * 2 + k];
        }
    }
}

// smem sizing (uint32 units)
#define TILE64_U32  (64 * PAD)                       // 2304
#define TILE128_U32 (128 * PAD)                      // 4608
#define G1_SMEM_U32 (128 + 2 * (TILE128_U32 + 2 * TILE64_U32))   // 18560 u32 = 74.2 KB
#define G2_SMEM_U32 (256 + 2 * 2 * TILE128_U32)                  // 18688 u32 = 74.8 KB
#define G1_SMEM_BYTES (G1_SMEM_U32 * 4)
#define G2_SMEM_BYTES (G2_SMEM_U32 * 4)

// ================= GEMM1: inter = silu(X w1^T) * (X w3^T) =================
// 256 threads, 2 CTAs/SM. Block 128x64, warps 4(M)x2(N), warp tile 32x32 dual, KC=32.
// R8 recipe: LDG -> cvt.rna (producer) -> STS; ldmatrix consumer (no cvt in chain).
__global__ __launch_bounds__(256, 2)
void gemm1_tc(const float* __restrict__ x,
              const float* __restrict__ w1,
              const float* __restrict__ w3) {
    int e = blockIdx.z;
    int cnt = g_count[e];
    int m0 = blockIdx.y * 128;
    if (m0 >= cnt) return;
    int n0 = blockIdx.x * 64;
    int base = g_offset[e];

    extern __shared__ uint32_t sm[];
    int* toks = (int*)sm;
    uint32_t* Abuf  = sm + 128;                             // 2 x TILE128
    uint32_t* B1buf = Abuf  + 2 * TILE128_U32;              // 2 x TILE64
    uint32_t* B3buf = B1buf + 2 * TILE64_U32;               // 2 x TILE64

    uint32_t sbA  = smem_u32(Abuf);
    uint32_t sbB1 = smem_u32(B1buf);
    uint32_t sbB3 = smem_u32(B3buf);

    int tid = threadIdx.x;
    int wid = tid >> 5, lane = tid & 31;
    int g = lane >> 2, tq = lane & 3;
    int grp = lane >> 3, rowi = lane & 7;
    int warpM = wid >> 1, warpN = wid & 1;     // 4(M) x 2(N)

    if (tid < 128) {
        int m = m0 + tid;
        toks[tid] = (m < cnt) ? g_tok[base + m] : -1;
    }
    __syncthreads();

    const float* W1 = w1 + (size_t)e * FF * DM + (size_t)n0 * DM;
    const float* W3 = w3 + (size_t)e * FF * DM + (size_t)n0 * DM;

    float acc1[2][4][4], acc3[2][4][4];
    #pragma unroll
    for (int i = 0; i < 2; i++)
        #pragma unroll
        for (int j = 0; j < 4; j++)
            #pragma unroll
            for (int c = 0; c < 4; c++) { acc1[i][j][c] = 0.f; acc3[i][j][c] = 0.f; }

    // producers: A 128 rows x 8 f4 (2 thr/row, 4 f4 each); B1/B3 64 rows x 8 f4 (4 thr/row, 2 f4 each)
    int arow = tid >> 1;                 // 0..127
    int aj0  = (tid & 1) * 4;            // f4 start
    int brow = tid >> 2;                 // 0..63
    int bj0  = (tid & 3) * 2;
    int atok = toks[arow];
    const float* aSrc  = x + (size_t)(atok >= 0 ? atok : 0) * DM;
    const float* b1Src = W1 + (size_t)brow * DM;
    const float* b3Src = W3 + (size_t)brow * DM;

    float4 ra[4], rb1[2], rb3[2];
    auto ldg_chunk = [&](int k0) {
        #pragma unroll
        for (int j = 0; j < 4; j++) {
            ra[j] = make_float4(0.f, 0.f, 0.f, 0.f);
            if (atok >= 0) ra[j] = *(const float4*)(aSrc + k0 + (aj0 + j) * 4);
        }
        #pragma unroll
        for (int j = 0; j < 2; j++) {
            rb1[j] = *(const float4*)(b1Src + k0 + (bj0 + j) * 4);
            rb3[j] = *(const float4*)(b3Src + k0 + (bj0 + j) * 4);
        }
    };
    auto sts_chunk = [&](int buf) {
        uint32_t* A  = Abuf  + buf * TILE128_U32;
        uint32_t* B1 = B1buf + buf * TILE64_U32;
        uint32_t* B3 = B3buf + buf * TILE64_U32;
        #pragma unroll
        for (int j = 0; j < 4; j++)
            *(uint4*)(A + arow * PAD + (aj0 + j) * 4) = to_tf32_v4(ra[j]);
        #pragma unroll
        for (int j = 0; j < 2; j++) {
            *(uint4*)(B1 + brow * PAD + (bj0 + j) * 4) = to_tf32_v4(rb1[j]);
            *(uint4*)(B3 + brow * PAD + (bj0 + j) * 4) = to_tf32_v4(rb3[j]);
        }
    };

    uint32_t aOff = (uint32_t)((warpM * 32 + (grp & 1) * 8 + rowi) * PAD + (grp >> 1) * 4) * 4;
    uint32_t bOff = (uint32_t)((warpN * 32 + (grp >> 1) * 8 + rowi) * PAD + (grp & 1) * 4) * 4;

    auto compute_chunk = [&](int buf) {
        uint32_t Ab  = sbA  + (uint32_t)(buf * TILE128_U32) * 4 + aOff;
        uint32_t B1b = sbB1 + (uint32_t)(buf * TILE64_U32) * 4 + bOff;
        uint32_t B3b = sbB3 + (uint32_t)(buf * TILE64_U32) * 4 + bOff;
        #pragma unroll
        for (int ks = 0; ks < 4; ks++) {
            uint32_t kb = (uint32_t)(ks * 32);
            uint32_t afr[2][4];
            #pragma unroll
            for (int mt = 0; mt < 2; mt++)
                ldsm_x4(Ab + kb + (uint32_t)(mt * 16 * PAD * 4), afr[mt]);
            uint32_t b1f[2][4], b3f[2][4];
            #pragma unroll
            for (int np = 0; np < 2; np++) {
                uint32_t off = kb + (uint32_t)(np * 16 * PAD * 4);
                ldsm_x4(B1b + off, b1f[np]);
                ldsm_x4(B3b + off, b3f[np]);
            }
            #pragma unroll
            for (int np = 0; np < 2; np++) {
                #pragma unroll
                for (int sub = 0; sub < 2; sub++) {
                    int nt = np * 2 + sub;
                    #pragma unroll
                    for (int mt = 0; mt < 2; mt++) {
                        mma_tf32(acc1[mt][nt], afr[mt], &b1f[np][sub * 2]);
                        mma_tf32(acc3[mt][nt], afr[mt], &b3f[np][sub * 2]);
                    }
                }
            }
        }
    };

    const int NIT = DM / KC;   // 32
    ldg_chunk(0);
    sts_chunk(0);
    __syncthreads();
    for (int it = 0; it < NIT; ++it) {
        if (it + 1 < NIT) ldg_chunk((it + 1) * KC);
        compute_chunk(it & 1);
        if (it + 1 < NIT) sts_chunk((it + 1) & 1);
        __syncthreads();
    }

    // epilogue: silu(up) * gate -> g_inter (valid rows only)
    #pragma unroll
    for (int mt = 0; mt < 2; mt++) {
        #pragma unroll
        for (int half = 0; half < 2; half++) {
            int rl = warpM * 32 + mt * 16 + half * 8 + g;
            int m = m0 + rl;
            if (m < cnt) {
                float* orow = g_inter + (size_t)(base + m) * FF + n0;
                #pragma unroll
                for (int nt = 0; nt < 4; nt++) {
                    int col = warpN * 32 + nt * 8 + 2 * tq;
                    float u0 = acc1[mt][nt][half * 2 + 0];
                    float u1 = acc1[mt][nt][half * 2 + 1];
                    float g0 = acc3[mt][nt][half * 2 + 0];
                    float g1 = acc3[mt][nt][half * 2 + 1];
                    float2 o;
                    o.x = u0 / (1.f + __expf(-u0)) * g0;
                    o.y = u1 / (1.f + __expf(-u1)) * g1;
                    *(float2*)(orow + col) = o;
                }
            }
        }
    }
}

// ================= GEMM2: out += cw * (inter w2^T) =================
// 256 threads, 2 CTAs/SM. Block 128x128, warps 2(M)x4(N), warp tile 64x32, KC=32.
__global__ __launch_bounds__(256, 2)
void gemm2_tc(const float* __restrict__ w2, float* __restrict__ out) {
    int e = blockIdx.z;
    int cnt = g_count[e];
    int m0 = blockIdx.y * 128;
    if (m0 >= cnt) return;
    int n0 = blockIdx.x * 128;
    int base = g_offset[e];

    extern __shared__ uint32_t sm[];
    int*   toks = (int*)sm;                     // [128]
    float* wgts = (float*)(sm + 128);           // [128]
    uint32_t* Abuf = sm + 256;                  // 2 x TILE128
    uint32_t* Bbuf = Abuf + 2 * TILE128_U32;    // 2 x TILE128

    uint32_t sbA = smem_u32(Abuf);
    uint32_t sbB = smem_u32(Bbuf);

    int tid = threadIdx.x;
    int wid = tid >> 5, lane = tid & 31;
    int g = lane >> 2, tq = lane & 3;
    int grp = lane >> 3, rowi = lane & 7;
    int warpM = wid >> 2, warpN = wid & 3;   // 2(M) x 4(N)

    if (tid < 128) {
        int m = m0 + tid;
        bool v = (m < cnt);
        toks[tid] = v ? g_tok[base + m] : -1;
        wgts[tid] = v ? g_wgt[base + m] : 0.f;
    }
    __syncthreads();

    const float* W2 = w2 + (size_t)e * DM * FF + (size_t)n0 * FF;
    const float* Ain = g_inter + (size_t)(base + m0) * FF;
    int mlim = cnt - m0;

    float acc[4][4][4];
    #pragma unroll
    for (int i = 0; i < 4; i++)
        #pragma unroll
        for (int j = 0; j < 4; j++)
            #pragma unroll
            for (int c = 0; c < 4; c++) acc[i][j][c] = 0.f;

    // producers: A 128 rows x 8 f4 (2 thr/row, 4 f4 each); B 128 rows x 8 f4 (same)
    int prow = tid >> 1;
    int pj0  = (tid & 1) * 4;
    bool aval = (prow < mlim);
    const float* aSrc = Ain + (size_t)(aval ? prow : 0) * FF;
    const float* bSrc = W2 + (size_t)prow * FF;

    float4 ra[4], rb[4];
    auto ldg_chunk = [&](int k0) {
        #pragma unroll
        for (int j = 0; j < 4; j++) {
            ra[j] = make_float4(0.f, 0.f, 0.f, 0.f);
            if (aval) ra[j] = *(const float4*)(aSrc + k0 + (pj0 + j) * 4);
            rb[j] = *(const float4*)(bSrc + k0 + (pj0 + j) * 4);
        }
    };
    auto sts_chunk = [&](int buf) {
        uint32_t* A = Abuf + buf * TILE128_U32;
        uint32_t* B = Bbuf + buf * TILE128_U32;
        #pragma unroll
        for (int j = 0; j < 4; j++) {
            *(uint4*)(A + prow * PAD + (pj0 + j) * 4) = to_tf32_v4(ra[j]);
            *(uint4*)(B + prow * PAD + (pj0 + j) * 4) = to_tf32_v4(rb[j]);
        }
    };

    uint32_t aOff = (uint32_t)((warpM * 64 + (grp & 1) * 8 + rowi) * PAD + (grp >> 1) * 4) * 4;
    uint32_t bOff = (uint32_t)((warpN * 32 + (grp >> 1) * 8 + rowi) * PAD + (grp & 1) * 4) * 4;

    auto compute_chunk = [&](int buf) {
        uint32_t Ab = sbA + (uint32_t)(buf * TILE128_U32) * 4 + aOff;
        uint32_t Bb = sbB + (uint32_t)(buf * TILE128_U32) * 4 + bOff;
        #pragma unroll
        for (int ks = 0; ks < 4; ks++) {
            uint32_t kb = (uint32_t)(ks * 32);
            uint32_t afr[4][4];
            #pragma unroll
            for (int mt = 0; mt < 4; mt++)
                ldsm_x4(Ab + kb + (uint32_t)(mt * 16 * PAD * 4), afr[mt]);
            uint32_t bf[2][4];
            #pragma unroll
            for (int np = 0; np < 2; np++)
                ldsm_x4(Bb + kb + (uint32_t)(np * 16 * PAD * 4), bf[np]);
            #pragma unroll
            for (int np = 0; np < 2; np++) {
                #pragma unroll
                for (int sub = 0; sub < 2; sub++) {
                    int nt = np * 2 + sub;
                    #pragma unroll
                    for (int mt = 0; mt < 4; mt++)
                        mma_tf32(acc[mt][nt], afr[mt], &bf[np][sub * 2]);
                }
            }
        }
    };

    const int NIT = FF / KC;   // 128
    ldg_chunk(0);
    sts_chunk(0);
    __syncthreads();
    for (int it = 0; it < NIT; ++it) {
        if (it + 1 < NIT) ldg_chunk((it + 1) * KC);
        compute_chunk(it & 1);
        if (it + 1 < NIT) sts_chunk((it + 1) & 1);
        __syncthreads();
    }

    // epilogue: weighted deterministic scatter-add (2 contributions per element)
    #pragma unroll
    for (int mt = 0; mt < 4; mt++) {
        #pragma unroll
        for (int half = 0; half < 2; half++) {
            int rl = warpM * 64 + mt * 16 + half * 8 + g;
            int t = toks[rl];
            if (t >= 0) {
                float w = wgts[rl];
                float* orow = out + (size_t)t * DM + n0;
                #pragma unroll
                for (int nt = 0; nt < 4; nt++) {
                    int col = warpN * 32 + nt * 8 + 2 * tq;
                    atomicAdd(orow + col,     w * acc[mt][nt][half * 2 + 0]);
                    atomicAdd(orow + col + 1, w * acc[mt][nt][half * 2 + 1]);
                }
            }
        }
    }
}

// ---------------- launch ----------------
extern "C" void kernel_launch(void* const* d_in, const int* in_sizes, int n_in,
                              void* d_out, int out_size) {
    const float* x  = (const float*)d_in[0];   // [T, DM]
    const float* gw = (const float*)d_in[1];   // [NE, DM]
    const float* w1 = (const float*)d_in[2];   // [NE, FF, DM]
    const float* w3 = (const float*)d_in[3];   // [NE, FF, DM]
    const float* w2 = (const float*)d_in[4];   // [NE, DM, FF]

    float* out    = (float*)d_out;             // [T, DM] then router_logits [T, NE]
    float* logits = out + (size_t)T * DM;

    cudaFuncSetAttribute(gemm1_tc, cudaFuncAttributeMaxDynamicSharedMemorySize, G1_SMEM_BYTES);
    cudaFuncSetAttribute(gemm2_tc, cudaFuncAttributeMaxDynamicSharedMemorySize, G2_SMEM_BYTES);

    cudaMemsetAsync(d_out, 0, (size_t)T * DM * sizeof(float));
    init_kernel<<<1, 32>>>();
    router_kernel<<<T, 256>>>(x, gw, logits);
    assign_kernel<<<1, 256>>>();
    gemm1_tc<<<dim3(FF / 64, (2 * T) / 128, NE), 256, G1_SMEM_BYTES>>>(x, w1, w3);
    gemm2_tc<<<dim3(DM / 128, (2 * T) / 128, NE), 256, G2_SMEM_BYTES>>>(w2, out);
}

// round 14
// speedup vs baseline: 1.1030x; 1.1030x over previous
#include <cuda_runtime.h>
#include <cuda_fp16.h>
#include <cstdint>
#include <math.h>

// Problem constants (fixed shapes)
#define T    2048
#define DM   1024
#define NE   8
#define FF   4096

// ---------------- scratch (static device globals; no allocation) ----------------
__device__ int    g_count[NE];
__device__ int    g_cursor[NE];
__device__ int    g_offset[NE];
__device__ int    g_topk_idx[T * 2];
__device__ float  g_topk_w[T * 2];
__device__ int    g_tok[2 * T];
__device__ float  g_wgt[2 * T];
__device__ __half g_inter[(size_t)(2 * T) * FF];   // 33 MB fp16 scratch

#define DEVINL __device__ __forceinline__

DEVINL uint32_t smem_u32(const void* p) {
    uint32_t a;
    asm("{ .reg .u64 t; cvta.to.shared.u64 t, %1; cvt.u32.u64 %0, t; }" : "=r"(a) : "l"(p));
    return a;
}

DEVINL uint32_t pack2(float a, float b) {
    __half2 h = __floats2half2_rn(a, b);
    return *reinterpret_cast<uint32_t*>(&h);
}
// 8 floats (two float4) -> uint4 of 8 halves
DEVINL uint4 pack8(float4 a, float4 b) {
    return make_uint4(pack2(a.x, a.y), pack2(a.z, a.w), pack2(b.x, b.y), pack2(b.z, b.w));
}

// fp16 tensor-core mma: D(f32) += A(f16) * B(f16)
DEVINL void mma_f16(float* d, const uint32_t* a, const uint32_t* b) {
    asm volatile(
        "mma.sync.aligned.m16n8k16.row.col.f32.f16.f16.f32 "
        "{%0,%1,%2,%3}, {%4,%5,%6,%7}, {%8,%9}, {%0,%1,%2,%3};"
        : "+f"(d[0]), "+f"(d[1]), "+f"(d[2]), "+f"(d[3])
        : "r"(a[0]), "r"(a[1]), "r"(a[2]), "r"(a[3]), "r"(b[0]), "r"(b[1]));
}

DEVINL void ldsm_x4(uint32_t addr, uint32_t* r) {
    asm volatile("ldmatrix.sync.aligned.m8n8.x4.shared.b16 {%0,%1,%2,%3}, [%4];"
        : "=r"(r[0]), "=r"(r[1]), "=r"(r[2]), "=r"(r[3]) : "r"(addr));
}

// ---------------- init ----------------
__global__ void init_kernel() {
    int i = threadIdx.x;
    if (i < NE) { g_count[i] = 0; g_cursor[i] = 0; }
}

// ---------------- router ----------------
__global__ void router_kernel(const float* __restrict__ x,
                              const float* __restrict__ gw,
                              float* __restrict__ logits_out) {
    int t = blockIdx.x;
    int warp = threadIdx.x >> 5;
    int lane = threadIdx.x & 31;
    const float* xr = x + (size_t)t * DM;
    const float* gr = gw + (size_t)warp * DM;
    float s = 0.f;
    for (int j = lane; j < DM; j += 32) s += xr[j] * gr[j];
    #pragma unroll
    for (int o = 16; o > 0; o >>= 1) s += __shfl_xor_sync(0xFFFFFFFFu, s, o);

    __shared__ float lg[NE];
    if (lane == 0) lg[warp] = s;
    __syncthreads();

    if (threadIdx.x == 0) {
        float mx = lg[0];
        #pragma unroll
        for (int e = 1; e < NE; e++) mx = fmaxf(mx, lg[e]);
        float p[NE];
        #pragma unroll
        for (int e = 0; e < NE; e++) p[e] = expf(lg[e] - mx);
        int i0 = 0;
        #pragma unroll
        for (int e = 1; e < NE; e++) if (p[e] > p[i0]) i0 = e;
        int i1 = -1;
        #pragma unroll
        for (int e = 0; e < NE; e++) {
            if (e == i0) continue;
            if (i1 < 0 || p[e] > p[i1]) i1 = e;
        }
        float inv = 1.f / (p[i0] + p[i1]);
        g_topk_idx[t * 2 + 0] = i0;
        g_topk_idx[t * 2 + 1] = i1;
        g_topk_w[t * 2 + 0] = p[i0] * inv;
        g_topk_w[t * 2 + 1] = p[i1] * inv;
        atomicAdd(&g_count[i0], 1);
        atomicAdd(&g_count[i1], 1);
        #pragma unroll
        for (int e = 0; e < NE; e++) logits_out[(size_t)t * NE + e] = lg[e];
    }
}

// ---------------- offsets + assignment (single block) ----------------
__global__ void assign_kernel() {
    if (threadIdx.x == 0) {
        int o = 0;
        #pragma unroll
        for (int e = 0; e < NE; e++) { g_offset[e] = o; o += g_count[e]; }
    }
    __syncthreads();
    for (int t = threadIdx.x; t < T; t += blockDim.x) {
        #pragma unroll
        for (int k = 0; k < 2; k++) {
            int e = g_topk_idx[t * 2 + k];
            int pos = atomicAdd(&g_cursor[e], 1);
            int g = g_offset[e] + pos;
            g_tok[g] = t;
            g_wgt[g] = g_topk_w[t * 2 + k];
        }
    }
}

// ===== GEMM1 smem: KC=32 halves, row = 40 halves (80 B; conflict-free ldsm)
#define G1_ROWH  40
#define G1_ROWB  80
#define G1_TILEB (128 * G1_ROWB)                    // 10240 B
#define G1_SMEM_BYTES (512 + 2 * 3 * G1_TILEB)      // 61952 B
// ===== GEMM2 smem: KC=64 halves, row = 72 halves (144 B; conflict-free ldsm)
#define G2_ROWH  72
#define G2_ROWB  144
#define G2_ATILEB (256 * G2_ROWB)                   // 36864 B
#define G2_BTILEB (128 * G2_ROWB)                   // 18432 B
#define G2_SMEM_BYTES (2048 + 2 * (G2_ATILEB + G2_BTILEB))   // 112640 B

// ================= GEMM1 (fp16 mma): inter = silu(X w1^T) * (X w3^T) =================
// 512 threads, 16 warps (4M x 4N), block 128x128, warp tile 32x32 dual-acc, KC=32.
__global__ __launch_bounds__(512, 1)
void gemm1_tc(const float* __restrict__ x,
              const float* __restrict__ w1,
              const float* __restrict__ w3) {
    int e = blockIdx.z;
    int cnt = g_count[e];
    int m0 = blockIdx.y * 128;
    if (m0 >= cnt) return;
    int n0 = blockIdx.x * 128;
    int base = g_offset[e];

    extern __shared__ char smc[];
    int* toks = (int*)smc;
    char* Abuf  = smc + 512;
    char* B1buf = Abuf  + 2 * G1_TILEB;
    char* B3buf = B1buf + 2 * G1_TILEB;
    uint32_t sbA  = smem_u32(Abuf);
    uint32_t sbB1 = smem_u32(B1buf);
    uint32_t sbB3 = smem_u32(B3buf);

    int tid = threadIdx.x;
    int wid = tid >> 5, lane = tid & 31;
    int g = lane >> 2, tq = lane & 3;
    int grp = lane >> 3, rowi = lane & 7;
    int warpM = wid >> 2, warpN = wid & 3;     // 4(M) x 4(N)

    if (tid < 128) {
        int m = m0 + tid;
        toks[tid] = (m < cnt) ? g_tok[base + m] : -1;
    }
    __syncthreads();

    const float* W1 = w1 + (size_t)e * FF * DM + (size_t)n0 * DM;
    const float* W3 = w3 + (size_t)e * FF * DM + (size_t)n0 * DM;

    float acc1[2][4][4], acc3[2][4][4];
    #pragma unroll
    for (int i = 0; i < 2; i++)
        #pragma unroll
        for (int j = 0; j < 4; j++)
            #pragma unroll
            for (int c = 0; c < 4; c++) { acc1[i][j][c] = 0.f; acc3[i][j][c] = 0.f; }

    // producer: per tile 128 rows x 32 halves (64 B/row); 4 thr/row x 16 B
    int prow = tid >> 2;
    int pq   = tid & 3;
    int ptok = toks[prow];
    const float* aSrc  = x + (size_t)(ptok >= 0 ? ptok : 0) * DM;
    const float* b1Src = W1 + (size_t)prow * DM;
    const float* b3Src = W3 + (size_t)prow * DM;
    uint32_t pd = (uint32_t)(prow * G1_ROWB + pq * 16);   // byte offset (8 halves)
    int pk = pq * 8;                                       // float offset within chunk

    float4 ra0, ra1, rb10, rb11, rb30, rb31;
    auto ldg_chunk = [&](int k0) {
        ra0 = make_float4(0.f, 0.f, 0.f, 0.f);
        ra1 = ra0;
        if (ptok >= 0) {
            ra0 = *(const float4*)(aSrc + k0 + pk);
            ra1 = *(const float4*)(aSrc + k0 + pk + 4);
        }
        rb10 = *(const float4*)(b1Src + k0 + pk);
        rb11 = *(const float4*)(b1Src + k0 + pk + 4);
        rb30 = *(const float4*)(b3Src + k0 + pk);
        rb31 = *(const float4*)(b3Src + k0 + pk + 4);
    };
    auto sts_chunk = [&](int buf) {
        uint32_t off = (uint32_t)(buf * G1_TILEB) + pd;
        *(uint4*)(Abuf  + off) = pack8(ra0, ra1);
        *(uint4*)(B1buf + off) = pack8(rb10, rb11);
        *(uint4*)(B3buf + off) = pack8(rb30, rb31);
    };

    // fragment byte offsets (A: m16k16 tiles; B: x4 covers two n8 tiles)
    uint32_t aOff = (uint32_t)((warpM * 32 + (grp & 1) * 8 + rowi) * G1_ROWB + (grp >> 1) * 16);
    uint32_t bOff = (uint32_t)((warpN * 32 + (grp >> 1) * 8 + rowi) * G1_ROWB + (grp & 1) * 16);

    auto compute_chunk = [&](int buf) {
        uint32_t Ab  = sbA  + (uint32_t)(buf * G1_TILEB) + aOff;
        uint32_t B1b = sbB1 + (uint32_t)(buf * G1_TILEB) + bOff;
        uint32_t B3b = sbB3 + (uint32_t)(buf * G1_TILEB) + bOff;
        #pragma unroll
        for (int ks = 0; ks < 2; ks++) {           // k16 per iter, KC=32
            uint32_t kb = (uint32_t)(ks * 32);     // 16 halves = 32 B
            uint32_t afr[2][4];
            #pragma unroll
            for (int mt = 0; mt < 2; mt++)
                ldsm_x4(Ab + kb + (uint32_t)(mt * 16 * G1_ROWB), afr[mt]);
            uint32_t b1f[2][4], b3f[2][4];
            #pragma unroll
            for (int np = 0; np < 2; np++) {
                uint32_t off = kb + (uint32_t)(np * 16 * G1_ROWB);
                ldsm_x4(B1b + off, b1f[np]);
                ldsm_x4(B3b + off, b3f[np]);
            }
            #pragma unroll
            for (int np = 0; np < 2; np++) {
                #pragma unroll
                for (int sub = 0; sub < 2; sub++) {
                    int nt = np * 2 + sub;
                    #pragma unroll
                    for (int mt = 0; mt < 2; mt++) {
                        mma_f16(acc1[mt][nt], afr[mt], &b1f[np][sub * 2]);
                        mma_f16(acc3[mt][nt], afr[mt], &b3f[np][sub * 2]);
                    }
                }
            }
        }
    };

    const int NIT = DM / 32;   // 32
    ldg_chunk(0);
    sts_chunk(0);
    __syncthreads();
    for (int it = 0; it < NIT; ++it) {
        if (it + 1 < NIT) ldg_chunk((it + 1) * 32);
        compute_chunk(it & 1);
        if (it + 1 < NIT) sts_chunk((it + 1) & 1);
        __syncthreads();
    }

    // epilogue: silu(up) * gate -> g_inter (fp16, valid rows only)
    #pragma unroll
    for (int mt = 0; mt < 2; mt++) {
        #pragma unroll
        for (int half = 0; half < 2; half++) {
            int rl = warpM * 32 + mt * 16 + half * 8 + g;
            int m = m0 + rl;
            if (m < cnt) {
                __half* orow = g_inter + (size_t)(base + m) * FF + n0;
                #pragma unroll
                for (int nt = 0; nt < 4; nt++) {
                    int col = warpN * 32 + nt * 8 + 2 * tq;
                    float u0 = acc1[mt][nt][half * 2 + 0];
                    float u1 = acc1[mt][nt][half * 2 + 1];
                    float g0 = acc3[mt][nt][half * 2 + 0];
                    float g1 = acc3[mt][nt][half * 2 + 1];
                    float o0 = u0 / (1.f + __expf(-u0)) * g0;
                    float o1 = u1 / (1.f + __expf(-u1)) * g1;
                    *(uint32_t*)(orow + col) = pack2(o0, o1);
                }
            }
        }
    }
}

// ================= GEMM2 (fp16 mma): out += cw * (inter w2^T) =================
// 512 threads, 16 warps (4M x 4N), block 256x128, warp tile 64x32, KC=64.
__global__ __launch_bounds__(512, 1)
void gemm2_tc(const float* __restrict__ w2, float* __restrict__ out) {
    int e = blockIdx.z;
    int cnt = g_count[e];
    int m0 = blockIdx.y * 256;
    if (m0 >= cnt) return;
    int n0 = blockIdx.x * 128;
    int base = g_offset[e];

    extern __shared__ char smc[];
    int*   toks = (int*)smc;                  // [256]
    float* wgts = (float*)(smc + 1024);       // [256]
    char* Abuf = smc + 2048;                  // 2 x G2_ATILEB
    char* Bbuf = Abuf + 2 * G2_ATILEB;        // 2 x G2_BTILEB
    uint32_t sbA = smem_u32(Abuf);
    uint32_t sbB = smem_u32(Bbuf);

    int tid = threadIdx.x;
    int wid = tid >> 5, lane = tid & 31;
    int g = lane >> 2, tq = lane & 3;
    int grp = lane >> 3, rowi = lane & 7;
    int warpM = wid >> 2, warpN = wid & 3;   // 4(M) x 4(N)

    if (tid < 256) {
        int m = m0 + tid;
        bool v = (m < cnt);
        toks[tid] = v ? g_tok[base + m] : -1;
        wgts[tid] = v ? g_wgt[base + m] : 0.f;
    }
    __syncthreads();

    const float*  W2  = w2 + (size_t)e * DM * FF + (size_t)n0 * FF;
    const __half* Ain = g_inter + (size_t)(base + m0) * FF;
    int mlim = cnt - m0;

    float acc[4][4][4];
    #pragma unroll
    for (int i = 0; i < 4; i++)
        #pragma unroll
        for (int j = 0; j < 4; j++)
            #pragma unroll
            for (int c = 0; c < 4; c++) acc[i][j][c] = 0.f;

    // producers (KC = 64 halves = 128 B per row):
    // A (half source, no cvt): 256 rows; 2 thr/row, each moves 64 B (4 x uint4)
    int parow = tid >> 1;
    int ph    = tid & 1;
    bool paval = (parow < mlim);
    const __half* paSrc = Ain + (size_t)(paval ? parow : 0) * FF;
    int pah0 = ph * 32;                                    // half offset within chunk
    uint32_t pad0 = (uint32_t)(parow * G2_ROWB + ph * 64); // byte offset in smem row
    // B (float source, cvt): 128 rows; 4 thr/row, each 16 floats -> 32 B
    int pbrow = tid >> 2;
    int pbq   = tid & 3;
    const float* pbSrc = W2 + (size_t)pbrow * FF;
    uint32_t pbd = (uint32_t)(pbrow * G2_ROWB + pbq * 32);
    int pbk = pbq * 16;

    uint4 rga[4];
    float4 rb0, rb1, rb2, rb3;
    auto ldg_chunk = [&](int k0) {
        #pragma unroll
        for (int j = 0; j < 4; j++) rga[j] = make_uint4(0, 0, 0, 0);
        if (paval) {
            #pragma unroll
            for (int j = 0; j < 4; j++)
                rga[j] = *(const uint4*)(paSrc + k0 + pah0 + j * 8);
        }
        rb0 = *(const float4*)(pbSrc + k0 + pbk);
        rb1 = *(const float4*)(pbSrc + k0 + pbk + 4);
        rb2 = *(const float4*)(pbSrc + k0 + pbk + 8);
        rb3 = *(const float4*)(pbSrc + k0 + pbk + 12);
    };
    auto sts_chunk = [&](int buf) {
        char* A = Abuf + buf * G2_ATILEB;
        char* B = Bbuf + buf * G2_BTILEB;
        #pragma unroll
        for (int j = 0; j < 4; j++)
            *(uint4*)(A + pad0 + j * 16) = rga[j];
        *(uint4*)(B + pbd)      = pack8(rb0, rb1);
        *(uint4*)(B + pbd + 16) = pack8(rb2, rb3);
    };

    uint32_t aOff = (uint32_t)((warpM * 64 + (grp & 1) * 8 + rowi) * G2_ROWB + (grp >> 1) * 16);
    uint32_t bOff = (uint32_t)((warpN * 32 + (grp >> 1) * 8 + rowi) * G2_ROWB + (grp & 1) * 16);

    auto compute_chunk = [&](int buf) {
        uint32_t Ab = sbA + (uint32_t)(buf * G2_ATILEB) + aOff;
        uint32_t Bb = sbB + (uint32_t)(buf * G2_BTILEB) + bOff;
        #pragma unroll
        for (int ks = 0; ks < 4; ks++) {           // k16 per iter, KC=64
            uint32_t kb = (uint32_t)(ks * 32);
            uint32_t afr[4][4];
            #pragma unroll
            for (int mt = 0; mt < 4; mt++)
                ldsm_x4(Ab + kb + (uint32_t)(mt * 16 * G2_ROWB), afr[mt]);
            uint32_t bf[2][4];
            #pragma unroll
            for (int np = 0; np < 2; np++)
                ldsm_x4(Bb + kb + (uint32_t)(np * 16 * G2_ROWB), bf[np]);
            #pragma unroll
            for (int np = 0; np < 2; np++) {
                #pragma unroll
                for (int sub = 0; sub < 2; sub++) {
                    int nt = np * 2 + sub;
                    #pragma unroll
                    for (int mt = 0; mt < 4; mt++)
                        mma_f16(acc[mt][nt], afr[mt], &bf[np][sub * 2]);
                }
            }
        }
    };

    const int NIT = FF / 64;   // 64
    ldg_chunk(0);
    sts_chunk(0);
    __syncthreads();
    for (int it = 0; it < NIT; ++it) {
        if (it + 1 < NIT) ldg_chunk((it + 1) * 64);
        compute_chunk(it & 1);
        if (it + 1 < NIT) sts_chunk((it + 1) & 1);
        __syncthreads();
    }

    // epilogue: weighted deterministic scatter-add (2 contributions per element)
    #pragma unroll
    for (int mt = 0; mt < 4; mt++) {
        #pragma unroll
        for (int half = 0; half < 2; half++) {
            int rl = warpM * 64 + mt * 16 + half * 8 + g;
            int t = toks[rl];
            if (t >= 0) {
                float w = wgts[rl];
                float* orow = out + (size_t)t * DM + n0;
                #pragma unroll
                for (int nt = 0; nt < 4; nt++) {
                    int col = warpN * 32 + nt * 8 + 2 * tq;
                    atomicAdd(orow + col,     w * acc[mt][nt][half * 2 + 0]);
                    atomicAdd(orow + col + 1, w * acc[mt][nt][half * 2 + 1]);
                }
            }
        }
    }
}

// ---------------- launch ----------------
extern "C" void kernel_launch(void* const* d_in, const int* in_sizes, int n_in,
                              void* d_out, int out_size) {
    const float* x  = (const float*)d_in[0];   // [T, DM]
    const float* gw = (const float*)d_in[1];   // [NE, DM]
    const float* w1 = (const float*)d_in[2];   // [NE, FF, DM]
    const float* w3 = (const float*)d_in[3];   // [NE, FF, DM]
    const float* w2 = (const float*)d_in[4];   // [NE, DM, FF]

    float* out    = (float*)d_out;             // [T, DM] then router_logits [T, NE]
    float* logits = out + (size_t)T * DM;

    cudaFuncSetAttribute(gemm1_tc, cudaFuncAttributeMaxDynamicSharedMemorySize, G1_SMEM_BYTES);
    cudaFuncSetAttribute(gemm2_tc, cudaFuncAttributeMaxDynamicSharedMemorySize, G2_SMEM_BYTES);

    cudaMemsetAsync(d_out, 0, (size_t)T * DM * sizeof(float));
    init_kernel<<<1, 32>>>();
    router_kernel<<<T, 256>>>(x, gw, logits);
    assign_kernel<<<1, 256>>>();
    gemm1_tc<<<dim3(FF / 128, (2 * T) / 128, NE), 512, G1_SMEM_BYTES>>>(x, w1, w3);
    gemm2_tc<<<dim3(DM / 128, (2 * T) / 256, NE), 512, G2_SMEM_BYTES>>>(w2, out);
}

// round 15
// speedup vs baseline: 1.1380x; 1.0317x over previous
#include <cuda_runtime.h>
#include <cuda_fp16.h>
#include <cstdint>
#include <math.h>

// Problem constants (fixed shapes)
#define T    2048
#define DM   1024
#define NE   8
#define FF   4096

#define KC   32            // K floats per chunk
#define PAD  36            // smem row stride in floats (32 + 4)

// ---------------- scratch (static device globals; no allocation) ----------------
__device__ int    g_count[NE];
__device__ int    g_cursor[NE];
__device__ int    g_offset[NE];
__device__ int    g_topk_idx[T * 2];
__device__ float  g_topk_w[T * 2];
__device__ int    g_tok[2 * T];
__device__ float  g_wgt[2 * T];
__device__ __half g_inter[(size_t)(2 * T) * FF];   // 33 MB fp16 scratch

#define DEVINL __device__ __forceinline__

DEVINL uint32_t smem_u32(const void* p) {
    uint32_t a;
    asm("{ .reg .u64 t; cvta.to.shared.u64 t, %1; cvt.u32.u64 %0, t; }" : "=r"(a) : "l"(p));
    return a;
}

DEVINL uint32_t to_tf32(float f) {
    uint32_t r;
    asm("cvt.rna.tf32.f32 %0, %1;" : "=r"(r) : "f"(f));
    return r;
}
DEVINL uint4 to_tf32_v4(float4 v) {
    return make_uint4(to_tf32(v.x), to_tf32(v.y), to_tf32(v.z), to_tf32(v.w));
}
DEVINL uint32_t pack2(float a, float b) {
    __half2 h = __floats2half2_rn(a, b);
    return *reinterpret_cast<uint32_t*>(&h);
}

DEVINL void mma_tf32(float* d, const uint32_t* a, const uint32_t* b) {
    asm volatile(
        "mma.sync.aligned.m16n8k8.row.col.f32.tf32.tf32.f32 "
        "{%0,%1,%2,%3}, {%4,%5,%6,%7}, {%8,%9}, {%0,%1,%2,%3};"
        : "+f"(d[0]), "+f"(d[1]), "+f"(d[2]), "+f"(d[3])
        : "r"(a[0]), "r"(a[1]), "r"(a[2]), "r"(a[3]), "r"(b[0]), "r"(b[1]));
}

// ldmatrix x4: four 8x8 b16 tiles == four 8x4 fp32 tiles; matches tf32 frag layout.
DEVINL void ldsm_x4(uint32_t addr, uint32_t* r) {
    asm volatile("ldmatrix.sync.aligned.m8n8.x4.shared.b16 {%0,%1,%2,%3}, [%4];"
        : "=r"(r[0]), "=r"(r[1]), "=r"(r[2]), "=r"(r[3]) : "r"(addr));
}

// ---------------- init ----------------
__global__ void init_kernel() {
    int i = threadIdx.x;
    if (i < NE) { g_count[i] = 0; g_cursor[i] = 0; }
}

// ---------------- router ----------------
__global__ void router_kernel(const float* __restrict__ x,
                              const float* __restrict__ gw,
                              float* __restrict__ logits_out) {
    int t = blockIdx.x;
    int warp = threadIdx.x >> 5;
    int lane = threadIdx.x & 31;
    const float* xr = x + (size_t)t * DM;
    const float* gr = gw + (size_t)warp * DM;
    float s = 0.f;
    for (int j = lane; j < DM; j += 32) s += xr[j] * gr[j];
    #pragma unroll
    for (int o = 16; o > 0; o >>= 1) s += __shfl_xor_sync(0xFFFFFFFFu, s, o);

    __shared__ float lg[NE];
    if (lane == 0) lg[warp] = s;
    __syncthreads();

    if (threadIdx.x == 0) {
        float mx = lg[0];
        #pragma unroll
        for (int e = 1; e < NE; e++) mx = fmaxf(mx, lg[e]);
        float p[NE];
        #pragma unroll
        for (int e = 0; e < NE; e++) p[e] = expf(lg[e] - mx);
        int i0 = 0;
        #pragma unroll
        for (int e = 1; e < NE; e++) if (p[e] > p[i0]) i0 = e;
        int i1 = -1;
        #pragma unroll
        for (int e = 0; e < NE; e++) {
            if (e == i0) continue;
            if (i1 < 0 || p[e] > p[i1]) i1 = e;
        }
        float inv = 1.f / (p[i0] + p[i1]);
        g_topk_idx[t * 2 + 0] = i0;
        g_topk_idx[t * 2 + 1] = i1;
        g_topk_w[t * 2 + 0] = p[i0] * inv;
        g_topk_w[t * 2 + 1] = p[i1] * inv;
        atomicAdd(&g_count[i0], 1);
        atomicAdd(&g_count[i1], 1);
        #pragma unroll
        for (int e = 0; e < NE; e++) logits_out[(size_t)t * NE + e] = lg[e];
    }
}

// ---------------- offsets + assignment (single block) ----------------
__global__ void assign_kernel() {
    if (threadIdx.x == 0) {
        int o = 0;
        #pragma unroll
        for (int e = 0; e < NE; e++) { g_offset[e] = o; o += g_count[e]; }
    }
    __syncthreads();
    for (int t = threadIdx.x; t < T; t += blockDim.x) {
        #pragma unroll
        for (int k = 0; k < 2; k++) {
            int e = g_topk_idx[t * 2 + k];
            int pos = atomicAdd(&g_cursor[e], 1);
            int g = g_offset[e] + pos;
            g_tok[g] = t;
            g_wgt[g] = g_topk_w[t * 2 + k];
        }
    }
}

// smem sizing (uint32 units)
#define TILE128_U32 (128 * PAD)                      // 4608
#define TILE256_U32 (256 * PAD)                      // 9216
#define G1_SMEM_U32 (128 + 2 * 3 * TILE128_U32)      // toks + 2 stages x {A,B1,B3}
#define G2_SMEM_U32 (512 + 2 * (TILE256_U32 + TILE128_U32)) // toks+wgts + 2 stages x {A256,B128}
#define G1_SMEM_BYTES (G1_SMEM_U32 * 4)
#define G2_SMEM_BYTES (G2_SMEM_U32 * 4)

// ================= GEMM1 (tf32 mma.sync + ldmatrix): inter = silu(X w1^T) * (X w3^T) =====
// 512 threads, block 128x128, warp tile 32x32 (mt=2, nt=4), 16 warps.
__global__ __launch_bounds__(512, 1)
void gemm1_tc(const float* __restrict__ x,
              const float* __restrict__ w1,
              const float* __restrict__ w3) {
    int e = blockIdx.z;
    int cnt = g_count[e];
    int m0 = blockIdx.y * 128;
    if (m0 >= cnt) return;
    int n0 = blockIdx.x * 128;
    int base = g_offset[e];

    extern __shared__ uint32_t sm[];
    int* toks = (int*)sm;
    uint32_t* Abuf  = sm + 128;
    uint32_t* B1buf = sm + 128 + 2 * TILE128_U32;
    uint32_t* B3buf = sm + 128 + 4 * TILE128_U32;

    uint32_t sbA  = smem_u32(Abuf);
    uint32_t sbB1 = smem_u32(B1buf);
    uint32_t sbB3 = smem_u32(B3buf);

    int tid = threadIdx.x;
    int wid = tid >> 5, lane = tid & 31;
    int g = lane >> 2, tq = lane & 3;
    int grp = lane >> 3, rowi = lane & 7;     // ldmatrix groups
    int warpM = wid >> 2, warpN = wid & 3;    // 4x4 warps

    if (tid < 128) {
        int m = m0 + tid;
        toks[tid] = (m < cnt) ? g_tok[base + m] : -1;
    }
    __syncthreads();

    const float* W1 = w1 + (size_t)e * FF * DM + (size_t)n0 * DM;
    const float* W3 = w3 + (size_t)e * FF * DM + (size_t)n0 * DM;

    float acc1[2][4][4], acc3[2][4][4];
    #pragma unroll
    for (int i = 0; i < 2; i++)
        #pragma unroll
        for (int j = 0; j < 4; j++)
            #pragma unroll
            for (int c = 0; c < 4; c++) { acc1[i][j][c] = 0.f; acc3[i][j][c] = 0.f; }

    // producers: 1024 float4 per tile, 512 threads -> 2 per thread
    float4 ra[2], rb1[2], rb3[2];

    auto ldg_chunk = [&](int k0) {
        #pragma unroll
        for (int p = 0; p < 2; p++) {
            int f = tid + p * 512;
            int row = f >> 3, j = f & 7;
            int tk = toks[row];
            ra[p] = make_float4(0.f, 0.f, 0.f, 0.f);
            if (tk >= 0) ra[p] = *(const float4*)(x + (size_t)tk * DM + k0 + j * 4);
            rb1[p] = *(const float4*)(W1 + (size_t)row * DM + k0 + j * 4);
            rb3[p] = *(const float4*)(W3 + (size_t)row * DM + k0 + j * 4);
        }
    };
    auto sts_chunk = [&](int buf) {
        uint32_t* A  = Abuf  + buf * TILE128_U32;
        uint32_t* B1 = B1buf + buf * TILE128_U32;
        uint32_t* B3 = B3buf + buf * TILE128_U32;
        #pragma unroll
        for (int p = 0; p < 2; p++) {
            int f = tid + p * 512;
            int row = f >> 3, j = f & 7;
            uint32_t off = row * PAD + j * 4;
            *(uint4*)(A + off)  = to_tf32_v4(ra[p]);
            *(uint4*)(B1 + off) = to_tf32_v4(rb1[p]);
            *(uint4*)(B3 + off) = to_tf32_v4(rb3[p]);
        }
    };
    auto compute_chunk = [&](int buf) {
        uint32_t Ab  = sbA  + buf * TILE128_U32 * 4;
        uint32_t B1b = sbB1 + buf * TILE128_U32 * 4;
        uint32_t B3b = sbB3 + buf * TILE128_U32 * 4;
        #pragma unroll
        for (int ks = 0; ks < 4; ks++) {
            uint32_t afr[2][4];
            #pragma unroll
            for (int mt = 0; mt < 2; mt++) {
                int arow = warpM * 32 + mt * 16 + (grp & 1) * 8 + rowi;
                uint32_t addr = Ab + (uint32_t)(arow * PAD + ks * 8 + (grp >> 1) * 4) * 4;
                ldsm_x4(addr, afr[mt]);
            }
            uint32_t b1f[2][4], b3f[2][4];
            #pragma unroll
            for (int np = 0; np < 2; np++) {
                int nrow = warpN * 32 + np * 16 + (grp >> 1) * 8 + rowi;
                uint32_t off = (uint32_t)(nrow * PAD + ks * 8 + (grp & 1) * 4) * 4;
                ldsm_x4(B1b + off, b1f[np]);
                ldsm_x4(B3b + off, b3f[np]);
            }
            #pragma unroll
            for (int np = 0; np < 2; np++) {
                #pragma unroll
                for (int sub = 0; sub < 2; sub++) {
                    int nt = np * 2 + sub;
                    #pragma unroll
                    for (int mt = 0; mt < 2; mt++) {
                        mma_tf32(acc1[mt][nt], afr[mt], &b1f[np][sub * 2]);
                        mma_tf32(acc3[mt][nt], afr[mt], &b3f[np][sub * 2]);
                    }
                }
            }
        }
    };

    const int NIT = DM / KC;   // 32
    ldg_chunk(0);
    sts_chunk(0);
    __syncthreads();
    for (int it = 0; it < NIT; ++it) {
        if (it + 1 < NIT) ldg_chunk((it + 1) * KC);
        compute_chunk(it & 1);
        if (it + 1 < NIT) sts_chunk((it + 1) & 1);
        __syncthreads();
    }

    // epilogue: silu(up) * gate -> g_inter as fp16 (valid rows only)
    #pragma unroll
    for (int mt = 0; mt < 2; mt++) {
        #pragma unroll
        for (int half = 0; half < 2; half++) {
            int rl = warpM * 32 + mt * 16 + half * 8 + g;
            int m = m0 + rl;
            if (m < cnt) {
                __half* orow = g_inter + (size_t)(base + m) * FF + n0;
                #pragma unroll
                for (int nt = 0; nt < 4; nt++) {
                    int col = warpN * 32 + nt * 8 + 2 * tq;
                    float u0 = acc1[mt][nt][half * 2 + 0];
                    float u1 = acc1[mt][nt][half * 2 + 1];
                    float g0 = acc3[mt][nt][half * 2 + 0];
                    float g1 = acc3[mt][nt][half * 2 + 1];
                    float o0 = u0 / (1.f + __expf(-u0)) * g0;
                    float o1 = u1 / (1.f + __expf(-u1)) * g1;
                    *(uint32_t*)(orow + col) = pack2(o0, o1);
                }
            }
        }
    }
}

// ================= GEMM2 (tf32 mma.sync + ldmatrix): out += cw * (inter w2^T) =============
// 512 threads, block 256x128, warp tile 64x32 (mt=4, nt=4), 16 warps.
// A source is fp16 g_inter: producer loads half2, cvt -> float -> tf32 -> STS.
__global__ __launch_bounds__(512, 1)
void gemm2_tc(const float* __restrict__ w2, float* __restrict__ out) {
    int e = blockIdx.z;
    int cnt = g_count[e];
    int m0 = blockIdx.y * 256;
    if (m0 >= cnt) return;
    int n0 = blockIdx.x * 128;
    int base = g_offset[e];

    extern __shared__ uint32_t sm[];
    int*   toks = (int*)sm;                 // [256]
    float* wgts = (float*)(sm + 256);       // [256]
    uint32_t* Abuf = sm + 512;                            // 2 x TILE256
    uint32_t* Bbuf = sm + 512 + 2 * TILE256_U32;          // 2 x TILE128

    uint32_t sbA = smem_u32(Abuf);
    uint32_t sbB = smem_u32(Bbuf);

    int tid = threadIdx.x;
    int wid = tid >> 5, lane = tid & 31;
    int g = lane >> 2, tq = lane & 3;
    int grp = lane >> 3, rowi = lane & 7;
    int warpM = wid >> 2, warpN = wid & 3;   // 4(M) x 4(N) warps

    if (tid < 256) {
        int m = m0 + tid;
        bool v = (m < cnt);
        toks[tid] = v ? g_tok[base + m] : -1;
        wgts[tid] = v ? g_wgt[base + m] : 0.f;
    }
    __syncthreads();

    const float*  W2  = w2 + (size_t)e * DM * FF + (size_t)n0 * FF;
    const __half* Ain = g_inter + (size_t)(base + m0) * FF;
    int mlim = cnt - m0;

    float acc[4][4][4];
    #pragma unroll
    for (int i = 0; i < 4; i++)
        #pragma unroll
        for (int j = 0; j < 4; j++)
            #pragma unroll
            for (int c = 0; c < 4; c++) acc[i][j][c] = 0.f;

    float4 ra[4], rb[2];
    auto ldg_chunk = [&](int k0) {
        #pragma unroll
        for (int p = 0; p < 4; p++) {               // A: 2048 cells (4 floats) / 512 thr
            int f = tid + p * 512;
            int row = f >> 3, j = f & 7;
            ra[p] = make_float4(0.f, 0.f, 0.f, 0.f);
            if (row < mlim) {
                // 4 halves = 8 bytes, aligned
                __half2 h01 = *(const __half2*)(Ain + (size_t)row * FF + k0 + j * 4);
                __half2 h23 = *(const __half2*)(Ain + (size_t)row * FF + k0 + j * 4 + 2);
                float2 f01 = __half22float2(h01);
                float2 f23 = __half22float2(h23);
                ra[p] = make_float4(f01.x, f01.y, f23.x, f23.y);
            }
        }
        #pragma unroll
        for (int p = 0; p < 2; p++) {               // B: 1024 f4 / 512 thr
            int f = tid + p * 512;
            int row = f >> 3, j = f & 7;
            rb[p] = *(const float4*)(W2 + (size_t)row * FF + k0 + j * 4);
        }
    };
    auto sts_chunk = [&](int buf) {
        uint32_t* A = Abuf + buf * TILE256_U32;
        uint32_t* B = Bbuf + buf * TILE128_U32;
        #pragma unroll
        for (int p = 0; p < 4; p++) {
            int f = tid + p * 512;
            int row = f >> 3, j = f & 7;
            *(uint4*)(A + row * PAD + j * 4) = to_tf32_v4(ra[p]);
        }
        #pragma unroll
        for (int p = 0; p < 2; p++) {
            int f = tid + p * 512;
            int row = f >> 3, j = f & 7;
            *(uint4*)(B + row * PAD + j * 4) = to_tf32_v4(rb[p]);
        }
    };
    auto compute_chunk = [&](int buf) {
        uint32_t Ab = sbA + buf * TILE256_U32 * 4;
        uint32_t Bb = sbB + buf * TILE128_U32 * 4;
        #pragma unroll
        for (int ks = 0; ks < 4; ks++) {
            uint32_t afr[4][4];
            #pragma unroll
            for (int mt = 0; mt < 4; mt++) {
                int arow = warpM * 64 + mt * 16 + (grp & 1) * 8 + rowi;
                uint32_t addr = Ab + (uint32_t)(arow * PAD + ks * 8 + (grp >> 1) * 4) * 4;
                ldsm_x4(addr, afr[mt]);
            }
            uint32_t bf[2][4];
            #pragma unroll
            for (int np = 0; np < 2; np++) {
                int nrow = warpN * 32 + np * 16 + (grp >> 1) * 8 + rowi;
                uint32_t off = (uint32_t)(nrow * PAD + ks * 8 + (grp & 1) * 4) * 4;
                ldsm_x4(Bb + off, bf[np]);
            }
            #pragma unroll
            for (int np = 0; np < 2; np++) {
                #pragma unroll
                for (int sub = 0; sub < 2; sub++) {
                    int nt = np * 2 + sub;
                    #pragma unroll
                    for (int mt = 0; mt < 4; mt++)
                        mma_tf32(acc[mt][nt], afr[mt], &bf[np][sub * 2]);
                }
            }
        }
    };

    const int NIT = FF / KC;   // 128
    ldg_chunk(0);
    sts_chunk(0);
    __syncthreads();
    for (int it = 0; it < NIT; ++it) {
        if (it + 1 < NIT) ldg_chunk((it + 1) * KC);
        compute_chunk(it & 1);
        if (it + 1 < NIT) sts_chunk((it + 1) & 1);
        __syncthreads();
    }

    // epilogue: weighted deterministic scatter-add (2 contributions per element)
    #pragma unroll
    for (int mt = 0; mt < 4; mt++) {
        #pragma unroll
        for (int half = 0; half < 2; half++) {
            int rl = warpM * 64 + mt * 16 + half * 8 + g;
            int t = toks[rl];
            if (t >= 0) {
                float w = wgts[rl];
                float* orow = out + (size_t)t * DM + n0;
                #pragma unroll
                for (int nt = 0; nt < 4; nt++) {
                    int col = warpN * 32 + nt * 8 + 2 * tq;
                    atomicAdd(orow + col,     w * acc[mt][nt][half * 2 + 0]);
                    atomicAdd(orow + col + 1, w * acc[mt][nt][half * 2 + 1]);
                }
            }
        }
    }
}

// ---------------- launch ----------------
extern "C" void kernel_launch(void* const* d_in, const int* in_sizes, int n_in,
                              void* d_out, int out_size) {
    const float* x  = (const float*)d_in[0];   // [T, DM]
    const float* gw = (const float*)d_in[1];   // [NE, DM]
    const float* w1 = (const float*)d_in[2];   // [NE, FF, DM]
    const float* w3 = (const float*)d_in[3];   // [NE, FF, DM]
    const float* w2 = (const float*)d_in[4];   // [NE, DM, FF]

    float* out    = (float*)d_out;             // [T, DM] then router_logits [T, NE]
    float* logits = out + (size_t)T * DM;

    cudaFuncSetAttribute(gemm1_tc, cudaFuncAttributeMaxDynamicSharedMemorySize, G1_SMEM_BYTES);
    cudaFuncSetAttribute(gemm2_tc, cudaFuncAttributeMaxDynamicSharedMemorySize, G2_SMEM_BYTES);

    cudaMemsetAsync(d_out, 0, (size_t)T * DM * sizeof(float));
    init_kernel<<<1, 32>>>();
    router_kernel<<<T, 256>>>(x, gw, logits);
    assign_kernel<<<1, 256>>>();
    gemm1_tc<<<dim3(FF / 128, (2 * T) / 128, NE), 512, G1_SMEM_BYTES>>>(x, w1, w3);
    gemm2_tc<<<dim3(DM / 128, (2 * T) / 256, NE), 512, G2_SMEM_BYTES>>>(w2, out);
}

// round 16
// speedup vs baseline: 1.2109x; 1.0641x over previous
#include <cuda_runtime.h>
#include <cuda_fp16.h>
#include <cstdint>
#include <math.h>

// Problem constants (fixed shapes)
#define T    2048
#define DM   1024
#define NE   8
#define FF   4096

#define KC   32            // K floats per chunk
#define PAD  36            // smem row stride in floats (32 + 4)

// ---------------- scratch (static device globals; no allocation) ----------------
__device__ int    g_count[NE];
__device__ int    g_cursor[NE];
__device__ int    g_offset[NE];
__device__ int    g_topk_idx[T * 2];
__device__ float  g_topk_w[T * 2];
__device__ int    g_tok[2 * T];
__device__ float  g_wgt[2 * T];
__device__ __half g_inter[(size_t)(2 * T) * FF];   // 33 MB fp16 scratch

#define DEVINL __device__ __forceinline__

DEVINL uint32_t smem_u32(const void* p) {
    uint32_t a;
    asm("{ .reg .u64 t; cvta.to.shared.u64 t, %1; cvt.u32.u64 %0, t; }" : "=r"(a) : "l"(p));
    return a;
}

DEVINL uint32_t to_tf32(float f) {
    uint32_t r;
    asm("cvt.rna.tf32.f32 %0, %1;" : "=r"(r) : "f"(f));
    return r;
}
DEVINL uint4 to_tf32_v4(float4 v) {
    return make_uint4(to_tf32(v.x), to_tf32(v.y), to_tf32(v.z), to_tf32(v.w));
}
DEVINL uint32_t pack2(float a, float b) {
    __half2 h = __floats2half2_rn(a, b);
    return *reinterpret_cast<uint32_t*>(&h);
}
// 8 halves (one uint4) -> two uint4 of tf32
DEVINL void h8_to_tf32(uint4 h, uint4* o0, uint4* o1) {
    const __half2* hp = reinterpret_cast<const __half2*>(&h);
    float2 f0 = __half22float2(hp[0]);
    float2 f1 = __half22float2(hp[1]);
    float2 f2 = __half22float2(hp[2]);
    float2 f3 = __half22float2(hp[3]);
    *o0 = make_uint4(to_tf32(f0.x), to_tf32(f0.y), to_tf32(f1.x), to_tf32(f1.y));
    *o1 = make_uint4(to_tf32(f2.x), to_tf32(f2.y), to_tf32(f3.x), to_tf32(f3.y));
}

DEVINL void mma_tf32(float* d, const uint32_t* a, const uint32_t* b) {
    asm volatile(
        "mma.sync.aligned.m16n8k8.row.col.f32.tf32.tf32.f32 "
        "{%0,%1,%2,%3}, {%4,%5,%6,%7}, {%8,%9}, {%0,%1,%2,%3};"
        : "+f"(d[0]), "+f"(d[1]), "+f"(d[2]), "+f"(d[3])
        : "r"(a[0]), "r"(a[1]), "r"(a[2]), "r"(a[3]), "r"(b[0]), "r"(b[1]));
}

// ldmatrix x4: four 8x8 b16 tiles == four 8x4 fp32 tiles; matches tf32 frag layout.
DEVINL void ldsm_x4(uint32_t addr, uint32_t* r) {
    asm volatile("ldmatrix.sync.aligned.m8n8.x4.shared.b16 {%0,%1,%2,%3}, [%4];"
        : "=r"(r[0]), "=r"(r[1]), "=r"(r[2]), "=r"(r[3]) : "r"(addr));
}

// ---------------- init ----------------
__global__ void init_kernel() {
    int i = threadIdx.x;
    if (i < NE) { g_count[i] = 0; g_cursor[i] = 0; }
}

// ---------------- router ----------------
__global__ void router_kernel(const float* __restrict__ x,
                              const float* __restrict__ gw,
                              float* __restrict__ logits_out) {
    int t = blockIdx.x;
    int warp = threadIdx.x >> 5;
    int lane = threadIdx.x & 31;
    const float* xr = x + (size_t)t * DM;
    const float* gr = gw + (size_t)warp * DM;
    float s = 0.f;
    for (int j = lane; j < DM; j += 32) s += xr[j] * gr[j];
    #pragma unroll
    for (int o = 16; o > 0; o >>= 1) s += __shfl_xor_sync(0xFFFFFFFFu, s, o);

    __shared__ float lg[NE];
    if (lane == 0) lg[warp] = s;
    __syncthreads();

    if (threadIdx.x == 0) {
        float mx = lg[0];
        #pragma unroll
        for (int e = 1; e < NE; e++) mx = fmaxf(mx, lg[e]);
        float p[NE];
        #pragma unroll
        for (int e = 0; e < NE; e++) p[e] = expf(lg[e] - mx);
        int i0 = 0;
        #pragma unroll
        for (int e = 1; e < NE; e++) if (p[e] > p[i0]) i0 = e;
        int i1 = -1;
        #pragma unroll
        for (int e = 0; e < NE; e++) {
            if (e == i0) continue;
            if (i1 < 0 || p[e] > p[i1]) i1 = e;
        }
        float inv = 1.f / (p[i0] + p[i1]);
        g_topk_idx[t * 2 + 0] = i0;
        g_topk_idx[t * 2 + 1] = i1;
        g_topk_w[t * 2 + 0] = p[i0] * inv;
        g_topk_w[t * 2 + 1] = p[i1] * inv;
        atomicAdd(&g_count[i0], 1);
        atomicAdd(&g_count[i1], 1);
        #pragma unroll
        for (int e = 0; e < NE; e++) logits_out[(size_t)t * NE + e] = lg[e];
    }
}

// ---------------- offsets + assignment (single block) ----------------
__global__ void assign_kernel() {
    if (threadIdx.x == 0) {
        int o = 0;
        #pragma unroll
        for (int e = 0; e < NE; e++) { g_offset[e] = o; o += g_count[e]; }
    }
    __syncthreads();
    for (int t = threadIdx.x; t < T; t += blockDim.x) {
        #pragma unroll
        for (int k = 0; k < 2; k++) {
            int e = g_topk_idx[t * 2 + k];
            int pos = atomicAdd(&g_cursor[e], 1);
            int g = g_offset[e] + pos;
            g_tok[g] = t;
            g_wgt[g] = g_topk_w[t * 2 + k];
        }
    }
}

// smem sizing (uint32 units)
#define TILE128_U32 (128 * PAD)                      // 4608
#define TILE256_U32 (256 * PAD)                      // 9216
#define G1_SMEM_U32 (128 + 2 * 3 * TILE128_U32)      // toks + 2 stages x {A,B1,B3}
#define G2_SMEM_U32 (512 + 2 * (TILE256_U32 + TILE128_U32)) // toks+wgts + 2 stages x {A256,B128}
#define G1_SMEM_BYTES (G1_SMEM_U32 * 4)
#define G2_SMEM_BYTES (G2_SMEM_U32 * 4)

// ================= GEMM1 (tf32 mma.sync + ldmatrix): inter = silu(X w1^T) * (X w3^T) =====
// 512 threads, block 128x128, warp tile 32x32 (mt=2, nt=4), 16 warps.  (R8 mainloop verbatim)
__global__ __launch_bounds__(512, 1)
void gemm1_tc(const float* __restrict__ x,
              const float* __restrict__ w1,
              const float* __restrict__ w3) {
    int e = blockIdx.z;
    int cnt = g_count[e];
    int m0 = blockIdx.y * 128;
    if (m0 >= cnt) return;
    int n0 = blockIdx.x * 128;
    int base = g_offset[e];

    extern __shared__ uint32_t sm[];
    int* toks = (int*)sm;
    uint32_t* Abuf  = sm + 128;
    uint32_t* B1buf = sm + 128 + 2 * TILE128_U32;
    uint32_t* B3buf = sm + 128 + 4 * TILE128_U32;

    uint32_t sbA  = smem_u32(Abuf);
    uint32_t sbB1 = smem_u32(B1buf);
    uint32_t sbB3 = smem_u32(B3buf);

    int tid = threadIdx.x;
    int wid = tid >> 5, lane = tid & 31;
    int g = lane >> 2, tq = lane & 3;
    int grp = lane >> 3, rowi = lane & 7;     // ldmatrix groups
    int warpM = wid >> 2, warpN = wid & 3;    // 4x4 warps

    if (tid < 128) {
        int m = m0 + tid;
        toks[tid] = (m < cnt) ? g_tok[base + m] : -1;
    }
    __syncthreads();

    const float* W1 = w1 + (size_t)e * FF * DM + (size_t)n0 * DM;
    const float* W3 = w3 + (size_t)e * FF * DM + (size_t)n0 * DM;

    float acc1[2][4][4], acc3[2][4][4];
    #pragma unroll
    for (int i = 0; i < 2; i++)
        #pragma unroll
        for (int j = 0; j < 4; j++)
            #pragma unroll
            for (int c = 0; c < 4; c++) { acc1[i][j][c] = 0.f; acc3[i][j][c] = 0.f; }

    // producers: 1024 float4 per tile, 512 threads -> 2 per thread
    float4 ra[2], rb1[2], rb3[2];

    auto ldg_chunk = [&](int k0) {
        #pragma unroll
        for (int p = 0; p < 2; p++) {
            int f = tid + p * 512;
            int row = f >> 3, j = f & 7;
            int tk = toks[row];
            ra[p] = make_float4(0.f, 0.f, 0.f, 0.f);
            if (tk >= 0) ra[p] = *(const float4*)(x + (size_t)tk * DM + k0 + j * 4);
            rb1[p] = *(const float4*)(W1 + (size_t)row * DM + k0 + j * 4);
            rb3[p] = *(const float4*)(W3 + (size_t)row * DM + k0 + j * 4);
        }
    };
    auto sts_chunk = [&](int buf) {
        uint32_t* A  = Abuf  + buf * TILE128_U32;
        uint32_t* B1 = B1buf + buf * TILE128_U32;
        uint32_t* B3 = B3buf + buf * TILE128_U32;
        #pragma unroll
        for (int p = 0; p < 2; p++) {
            int f = tid + p * 512;
            int row = f >> 3, j = f & 7;
            uint32_t off = row * PAD + j * 4;
            *(uint4*)(A + off)  = to_tf32_v4(ra[p]);
            *(uint4*)(B1 + off) = to_tf32_v4(rb1[p]);
            *(uint4*)(B3 + off) = to_tf32_v4(rb3[p]);
        }
    };
    auto compute_chunk = [&](int buf) {
        uint32_t Ab  = sbA  + buf * TILE128_U32 * 4;
        uint32_t B1b = sbB1 + buf * TILE128_U32 * 4;
        uint32_t B3b = sbB3 + buf * TILE128_U32 * 4;
        #pragma unroll
        for (int ks = 0; ks < 4; ks++) {
            uint32_t afr[2][4];
            #pragma unroll
            for (int mt = 0; mt < 2; mt++) {
                int arow = warpM * 32 + mt * 16 + (grp & 1) * 8 + rowi;
                uint32_t addr = Ab + (uint32_t)(arow * PAD + ks * 8 + (grp >> 1) * 4) * 4;
                ldsm_x4(addr, afr[mt]);
            }
            uint32_t b1f[2][4], b3f[2][4];
            #pragma unroll
            for (int np = 0; np < 2; np++) {
                int nrow = warpN * 32 + np * 16 + (grp >> 1) * 8 + rowi;
                uint32_t off = (uint32_t)(nrow * PAD + ks * 8 + (grp & 1) * 4) * 4;
                ldsm_x4(B1b + off, b1f[np]);
                ldsm_x4(B3b + off, b3f[np]);
            }
            #pragma unroll
            for (int np = 0; np < 2; np++) {
                #pragma unroll
                for (int sub = 0; sub < 2; sub++) {
                    int nt = np * 2 + sub;
                    #pragma unroll
                    for (int mt = 0; mt < 2; mt++) {
                        mma_tf32(acc1[mt][nt], afr[mt], &b1f[np][sub * 2]);
                        mma_tf32(acc3[mt][nt], afr[mt], &b3f[np][sub * 2]);
                    }
                }
            }
        }
    };

    const int NIT = DM / KC;   // 32
    ldg_chunk(0);
    sts_chunk(0);
    __syncthreads();
    for (int it = 0; it < NIT; ++it) {
        if (it + 1 < NIT) ldg_chunk((it + 1) * KC);
        compute_chunk(it & 1);
        if (it + 1 < NIT) sts_chunk((it + 1) & 1);
        __syncthreads();
    }

    // epilogue: silu(up) * gate -> g_inter as fp16 (valid rows only)
    #pragma unroll
    for (int mt = 0; mt < 2; mt++) {
        #pragma unroll
        for (int half = 0; half < 2; half++) {
            int rl = warpM * 32 + mt * 16 + half * 8 + g;
            int m = m0 + rl;
            if (m < cnt) {
                __half* orow = g_inter + (size_t)(base + m) * FF + n0;
                #pragma unroll
                for (int nt = 0; nt < 4; nt++) {
                    int col = warpN * 32 + nt * 8 + 2 * tq;
                    float u0 = acc1[mt][nt][half * 2 + 0];
                    float u1 = acc1[mt][nt][half * 2 + 1];
                    float g0 = acc3[mt][nt][half * 2 + 0];
                    float g1 = acc3[mt][nt][half * 2 + 1];
                    float o0 = u0 / (1.f + __expf(-u0)) * g0;
                    float o1 = u1 / (1.f + __expf(-u1)) * g1;
                    *(uint32_t*)(orow + col) = pack2(o0, o1);
                }
            }
        }
    }
}

// ================= GEMM2 (tf32 mma.sync + ldmatrix): out += cw * (inter w2^T) =============
// 512 threads, block 256x128, warp tile 64x32 (mt=4, nt=4), 16 warps.
// A source is fp16 g_inter: producer does 2x LDG.128 (16 halves) -> cvt -> tf32 -> STS.
__global__ __launch_bounds__(512, 1)
void gemm2_tc(const float* __restrict__ w2, float* __restrict__ out) {
    int e = blockIdx.z;
    int cnt = g_count[e];
    int m0 = blockIdx.y * 256;
    if (m0 >= cnt) return;
    int n0 = blockIdx.x * 128;
    int base = g_offset[e];

    extern __shared__ uint32_t sm[];
    int*   toks = (int*)sm;                 // [256]
    float* wgts = (float*)(sm + 256);       // [256]
    uint32_t* Abuf = sm + 512;                            // 2 x TILE256
    uint32_t* Bbuf = sm + 512 + 2 * TILE256_U32;          // 2 x TILE128

    uint32_t sbA = smem_u32(Abuf);
    uint32_t sbB = smem_u32(Bbuf);

    int tid = threadIdx.x;
    int wid = tid >> 5, lane = tid & 31;
    int g = lane >> 2, tq = lane & 3;
    int grp = lane >> 3, rowi = lane & 7;
    int warpM = wid >> 2, warpN = wid & 3;   // 4(M) x 4(N) warps

    if (tid < 256) {
        int m = m0 + tid;
        bool v = (m < cnt);
        toks[tid] = v ? g_tok[base + m] : -1;
        wgts[tid] = v ? g_wgt[base + m] : 0.f;
    }
    __syncthreads();

    const float*  W2  = w2 + (size_t)e * DM * FF + (size_t)n0 * FF;
    const __half* Ain = g_inter + (size_t)(base + m0) * FF;
    int mlim = cnt - m0;

    float acc[4][4][4];
    #pragma unroll
    for (int i = 0; i < 4; i++)
        #pragma unroll
        for (int j = 0; j < 4; j++)
            #pragma unroll
            for (int c = 0; c < 4; c++) acc[i][j][c] = 0.f;

    // A producer: 256 rows x 32 halves (64 B/row); 2 thr/row x 32 B (2 x uint4 of 8 halves)
    int parow = tid >> 1;
    int ph    = tid & 1;
    bool paval = (parow < mlim);
    const __half* paSrc = Ain + (size_t)(paval ? parow : 0) * FF;
    int pah = ph * 16;                                   // half offset within chunk
    uint32_t paOffS = (uint32_t)(parow * PAD + ph * 16); // float offset in smem row
    // B producer: 128 rows x 32 floats; 1024 f4 / 512 thr -> 2 each
    float4 rb[2];
    uint4 rha[2];

    auto ldg_chunk = [&](int k0) {
        rha[0] = make_uint4(0, 0, 0, 0);
        rha[1] = rha[0];
        if (paval) {
            rha[0] = *(const uint4*)(paSrc + k0 + pah);
            rha[1] = *(const uint4*)(paSrc + k0 + pah + 8);
        }
        #pragma unroll
        for (int p = 0; p < 2; p++) {
            int f = tid + p * 512;
            int row = f >> 3, j = f & 7;
            rb[p] = *(const float4*)(W2 + (size_t)row * FF + k0 + j * 4);
        }
    };
    auto sts_chunk = [&](int buf) {
        uint32_t* A = Abuf + buf * TILE256_U32;
        uint32_t* B = Bbuf + buf * TILE128_U32;
        uint4 o0, o1;
        h8_to_tf32(rha[0], &o0, &o1);
        *(uint4*)(A + paOffS)     = o0;
        *(uint4*)(A + paOffS + 4) = o1;
        h8_to_tf32(rha[1], &o0, &o1);
        *(uint4*)(A + paOffS + 8)  = o0;
        *(uint4*)(A + paOffS + 12) = o1;
        #pragma unroll
        for (int p = 0; p < 2; p++) {
            int f = tid + p * 512;
            int row = f >> 3, j = f & 7;
            *(uint4*)(B + row * PAD + j * 4) = to_tf32_v4(rb[p]);
        }
    };
    auto compute_chunk = [&](int buf) {
        uint32_t Ab = sbA + buf * TILE256_U32 * 4;
        uint32_t Bb = sbB + buf * TILE128_U32 * 4;
        #pragma unroll
        for (int ks = 0; ks < 4; ks++) {
            uint32_t afr[4][4];
            #pragma unroll
            for (int mt = 0; mt < 4; mt++) {
                int arow = warpM * 64 + mt * 16 + (grp & 1) * 8 + rowi;
                uint32_t addr = Ab + (uint32_t)(arow * PAD + ks * 8 + (grp >> 1) * 4) * 4;
                ldsm_x4(addr, afr[mt]);
            }
            uint32_t bf[2][4];
            #pragma unroll
            for (int np = 0; np < 2; np++) {
                int nrow = warpN * 32 + np * 16 + (grp >> 1) * 8 + rowi;
                uint32_t off = (uint32_t)(nrow * PAD + ks * 8 + (grp & 1) * 4) * 4;
                ldsm_x4(Bb + off, bf[np]);
            }
            #pragma unroll
            for (int np = 0; np < 2; np++) {
                #pragma unroll
                for (int sub = 0; sub < 2; sub++) {
                    int nt = np * 2 + sub;
                    #pragma unroll
                    for (int mt = 0; mt < 4; mt++)
                        mma_tf32(acc[mt][nt], afr[mt], &bf[np][sub * 2]);
                }
            }
        }
    };

    const int NIT = FF / KC;   // 128
    ldg_chunk(0);
    sts_chunk(0);
    __syncthreads();
    for (int it = 0; it < NIT; ++it) {
        if (it + 1 < NIT) ldg_chunk((it + 1) * KC);
        compute_chunk(it & 1);
        if (it + 1 < NIT) sts_chunk((it + 1) & 1);
        __syncthreads();
    }

    // epilogue: weighted deterministic scatter-add (2 contributions per element)
    #pragma unroll
    for (int mt = 0; mt < 4; mt++) {
        #pragma unroll
        for (int half = 0; half < 2; half++) {
            int rl = warpM * 64 + mt * 16 + half * 8 + g;
            int t = toks[rl];
            if (t >= 0) {
                float w = wgts[rl];
                float* orow = out + (size_t)t * DM + n0;
                #pragma unroll
                for (int nt = 0; nt < 4; nt++) {
                    int col = warpN * 32 + nt * 8 + 2 * tq;
                    atomicAdd(orow + col,     w * acc[mt][nt][half * 2 + 0]);
                    atomicAdd(orow + col + 1, w * acc[mt][nt][half * 2 + 1]);
                }
            }
        }
    }
}

// ---------------- launch ----------------
extern "C" void kernel_launch(void* const* d_in, const int* in_sizes, int n_in,
                              void* d_out, int out_size) {
    const float* x  = (const float*)d_in[0];   // [T, DM]
    const float* gw = (const float*)d_in[1];   // [NE, DM]
    const float* w1 = (const float*)d_in[2];   // [NE, FF, DM]
    const float* w3 = (const float*)d_in[3];   // [NE, FF, DM]
    const float* w2 = (const float*)d_in[4];   // [NE, DM, FF]

    float* out    = (float*)d_out;             // [T, DM] then router_logits [T, NE]
    float* logits = out + (size_t)T * DM;

    cudaFuncSetAttribute(gemm1_tc, cudaFuncAttributeMaxDynamicSharedMemorySize, G1_SMEM_BYTES);
    cudaFuncSetAttribute(gemm2_tc, cudaFuncAttributeMaxDynamicSharedMemorySize, G2_SMEM_BYTES);

    cudaMemsetAsync(d_out, 0, (size_t)T * DM * sizeof(float));
    init_kernel<<<1, 32>>>();
    router_kernel<<<T, 256>>>(x, gw, logits);
    assign_kernel<<<1, 256>>>();
    gemm1_tc<<<dim3(FF / 128, (2 * T) / 128, NE), 512, G1_SMEM_BYTES>>>(x, w1, w3);
    gemm2_tc<<<dim3(DM / 128, (2 * T) / 256, NE), 512, G2_SMEM_BYTES>>>(w2, out);
}